// round 3
// baseline (speedup 1.0000x reference)
#include <cuda_runtime.h>
#include <math.h>

// ---------------------------------------------------------------------------
// Shapes
//   x0: [2, 256, 32^3]   -> 512 channel-slices of 32768 elems
//   x1: [2, 128, 64^3]   -> 256 channel-slices of 262144 elems
//   x2: [2,  64, 128^3]  -> 128 channel-slices of 2097152 elems
// Partial layout (deterministic):
//   x2: 32 partials/slice -> 4096 at g_part[0]
//   x1:  4 partials/slice -> 1024 at g_part[4096]
//   x0:  1 partial/slice  ->  512 at g_part[5120]
// Fused single kernel: blocks 1..5632 reduce; block 0 prefetches weights,
// spins on g_count, then runs the epilogue (threadFenceReduction pattern).
// ---------------------------------------------------------------------------

__device__ float g_part[5632];
__device__ int   g_count = 0;
__device__ float g_dummy[4];     // sink to keep prefetch loads live

#define NBLK 5632

// --- 448-wide group sum for the epilogue (warps 0-13 = batch0, 14-27 = b1) --
__device__ __forceinline__ float gsum(float v, float* sbuf)
{
    #pragma unroll
    for (int o = 16; o; o >>= 1) v += __shfl_down_sync(0xffffffffu, v, o);
    int w = threadIdx.x >> 5;
    int lane = threadIdx.x & 31;
    if (lane == 0) sbuf[w] = v;
    __syncthreads();
    if (w == 0 || w == 14) {
        float x = (lane < 14) ? sbuf[w + lane] : 0.f;
        #pragma unroll
        for (int o = 16; o; o >>= 1) x += __shfl_down_sync(0xffffffffu, x, o);
        if (lane == 0) sbuf[w] = x;
    }
    __syncthreads();
    float r = sbuf[(threadIdx.x >= 448) ? 14 : 0];
    __syncthreads();
    return r;
}

__device__ __forceinline__ void ln(float* v, int n, int t,
                                   const float* __restrict__ w,
                                   const float* __restrict__ b,
                                   float* sbuf)
{
    float x   = (t < n) ? v[t] : 0.f;
    float mu  = gsum(x, sbuf) * (1.f / (float)n);
    float d   = (t < n) ? (x - mu) : 0.f;
    float var = gsum(d * d, sbuf) * (1.f / (float)n);
    float r   = rsqrtf(var + 1e-5f);
    if (t < n) v[t] = d * r * w[t] + b[t];
    __syncthreads();
}

__global__ __launch_bounds__(896, 1) void fused(
    const float* __restrict__ x0,
    const float* __restrict__ x1,
    const float* __restrict__ x2,
    const float* __restrict__ ln1w, const float* __restrict__ ln1b,
    const float* __restrict__ ln2w, const float* __restrict__ ln2b,
    const float* __restrict__ ln3w, const float* __restrict__ ln3b,
    const float* __restrict__ ln4w, const float* __restrict__ ln4b,
    const float* __restrict__ ln5w, const float* __restrict__ ln5b,
    const float* __restrict__ mlp_w1, const float* __restrict__ mlp_b1,
    const float* __restrict__ mlp_w2, const float* __restrict__ mlp_b2,
    const float* __restrict__ conv_w, const float* __restrict__ conv_b,
    float* __restrict__ out)
{
    int tid = threadIdx.x;

    // =======================================================================
    // Reducer blocks
    // =======================================================================
    if (blockIdx.x > 0) {
        int bid = blockIdx.x - 1;
        const float4* src;
        int nvec;
        if (bid < 4096) {                    // x2 chunks: 16384 float4
            src  = reinterpret_cast<const float4*>(x2) + (size_t)bid * 16384;
            nvec = 16384;
        } else if (bid < 5120) {             // x1 chunks: 16384 float4
            src  = reinterpret_cast<const float4*>(x1) + (size_t)(bid - 4096) * 16384;
            nvec = 16384;
        } else {                             // x0 chunks: 8192 float4
            src  = reinterpret_cast<const float4*>(x0) + (size_t)(bid - 5120) * 8192;
            nvec = 8192;
        }

        float s = 0.f;
        #pragma unroll 4
        for (int i = tid; i < nvec; i += 896) {
            float4 a = __ldcs(src + i);      // streaming: evict-first in L2
            s += (a.x + a.y) + (a.z + a.w);
        }

        __shared__ float rbuf[28];
        #pragma unroll
        for (int o = 16; o; o >>= 1) s += __shfl_down_sync(0xffffffffu, s, o);
        if ((tid & 31) == 0) rbuf[tid >> 5] = s;
        __syncthreads();
        if (tid < 32) {
            s = (tid < 28) ? rbuf[tid] : 0.f;
            #pragma unroll
            for (int o = 16; o; o >>= 1) s += __shfl_down_sync(0xffffffffu, s, o);
            if (tid == 0) {
                g_part[bid] = s;
                __threadfence();
                atomicAdd(&g_count, 1);
            }
        }
        return;
    }

    // =======================================================================
    // Block 0: prefetch weights -> spin -> epilogue
    // =======================================================================
    __shared__ float sv[2][448];
    __shared__ float h1s[2][64];
    __shared__ float red[2][448];
    __shared__ float sbuf[32];

    // --- Prefetch all epilogue weights into L1/L2 while reducers stream ---
    {
        float s = 0.f;
        const float4* w1 = reinterpret_cast<const float4*>(mlp_w1);
        const float4* w2 = reinterpret_cast<const float4*>(mlp_w2);
        const float4* wc = reinterpret_cast<const float4*>(conv_w);
        for (int i = tid; i < 7168; i += 896) {      // 28672 floats each
            float4 a = w1[i], bb = w2[i], cc = wc[i];
            s += a.x + bb.y + cc.z;
        }
        // LN params + biases (small)
        if (tid < 64)  s += ln1w[tid] + ln1b[tid] + mlp_b1[tid] + conv_b[tid];
        if (tid < 128) s += ln2w[tid] + ln2b[tid];
        if (tid < 256) s += ln3w[tid] + ln3b[tid];
        if (tid < 384) s += ln4w[tid] + ln4b[tid];
        if (tid < 448) s += ln5w[tid] + ln5b[tid] + mlp_b2[tid];
        if (s == 123456789.0f) g_dummy[0] = s;       // never true; keeps loads
    }

    // --- Spin until all 5632 partials are published ---
    if (tid == 0) {
        volatile int* cnt = &g_count;
        while (*cnt != NBLK) __nanosleep(200);
        __threadfence();
        g_count = 0;                                  // reset for graph replay
    }
    __syncthreads();

    int b = tid / 448;                                // warp-aligned batch
    int t = tid - b * 448;
    float* svb = sv[b];

    // --- Assemble raw GAP means (deterministic partial ordering) ---
    if (t < 64) {
        int base = (b * 64 + t) * 32;
        float s = 0.f;
        #pragma unroll
        for (int k = 0; k < 32; k++) s += g_part[base + k];
        svb[t] = s * (1.f / 2097152.f);
    }
    if (t < 128) {
        int base = 4096 + (b * 128 + t) * 4;
        float s = 0.f;
        #pragma unroll
        for (int k = 0; k < 4; k++) s += g_part[base + k];
        svb[64 + t] = s * (1.f / 262144.f);
    }
    if (t < 256) {
        svb[192 + t] = g_part[5120 + b * 256 + t] * (1.f / 32768.f);
    }
    __syncthreads();

    // --- LayerNorm chain (both batches in parallel) ---
    ln(svb,        64, t, ln1w, ln1b, sbuf);
    ln(svb +  64, 128, t, ln2w, ln2b, sbuf);
    ln(svb + 192, 256, t, ln3w, ln3b, sbuf);
    ln(svb +  64, 384, t, ln4w, ln4b, sbuf);
    ln(svb,       448, t, ln5w, ln5b, sbuf);

    int c = t >> 6;                   // inner chunk 0..6
    int i = t & 63;                   // output index 0..63

    // --- h1 = relu(out7 @ W1^T + b1) ---
    {
        const float4* w4 = reinterpret_cast<const float4*>(mlp_w1 + i * 448 + c * 64);
        const float4* x4 = reinterpret_cast<const float4*>(svb + c * 64);
        float p = 0.f;
        #pragma unroll
        for (int k = 0; k < 16; k++) {
            float4 wv = w4[k], xv = x4[k];
            p = fmaf(wv.x, xv.x, p); p = fmaf(wv.y, xv.y, p);
            p = fmaf(wv.z, xv.z, p); p = fmaf(wv.w, xv.w, p);
        }
        red[b][c * 64 + i] = p;
    }
    __syncthreads();
    if (t < 64) {
        float acc = mlp_b1[t];
        #pragma unroll
        for (int cc = 0; cc < 7; cc++) acc += red[b][cc * 64 + t];
        h1s[b][t] = fmaxf(acc, 0.f);
    }
    __syncthreads();

    // --- h2 = relu(h1 @ W2^T + b2) ---
    {
        float acc = mlp_b2[t];
        const float4* w4 = reinterpret_cast<const float4*>(mlp_w2 + t * 64);
        const float4* h4 = reinterpret_cast<const float4*>(h1s[b]);
        #pragma unroll
        for (int k = 0; k < 16; k++) {
            float4 wv = w4[k], hv = h4[k];
            acc = fmaf(wv.x, hv.x, acc); acc = fmaf(wv.y, hv.y, acc);
            acc = fmaf(wv.z, hv.z, acc); acc = fmaf(wv.w, hv.w, acc);
        }
        acc = fmaxf(acc, 0.f);
        __syncthreads();
        svb[t] = acc;
        __syncthreads();
    }

    // --- o = sigmoid(h2 @ Wc^T + bc) ---
    {
        const float4* w4 = reinterpret_cast<const float4*>(conv_w + i * 448 + c * 64);
        const float4* x4 = reinterpret_cast<const float4*>(svb + c * 64);
        float p = 0.f;
        #pragma unroll
        for (int k = 0; k < 16; k++) {
            float4 wv = w4[k], xv = x4[k];
            p = fmaf(wv.x, xv.x, p); p = fmaf(wv.y, xv.y, p);
            p = fmaf(wv.z, xv.z, p); p = fmaf(wv.w, xv.w, p);
        }
        red[b][c * 64 + i] = p;
    }
    __syncthreads();
    if (t < 64) {
        float acc = conv_b[t];
        #pragma unroll
        for (int cc = 0; cc < 7; cc++) acc += red[b][cc * 64 + t];
        out[b * 64 + t] = 1.f / (1.f + expf(-acc));
    }
}

// ---------------------------------------------------------------------------

extern "C" void kernel_launch(void* const* d_in, const int* in_sizes, int n_in,
                              void* d_out, int out_size)
{
    fused<<<NBLK + 1, 896>>>(
        (const float*)d_in[0], (const float*)d_in[1], (const float*)d_in[2],
        (const float*)d_in[3],  (const float*)d_in[4],   // ln1
        (const float*)d_in[5],  (const float*)d_in[6],   // ln2
        (const float*)d_in[7],  (const float*)d_in[8],   // ln3
        (const float*)d_in[9],  (const float*)d_in[10],  // ln4
        (const float*)d_in[11], (const float*)d_in[12],  // ln5
        (const float*)d_in[13], (const float*)d_in[14],  // mlp1
        (const float*)d_in[15], (const float*)d_in[16],  // mlp2
        (const float*)d_in[17], (const float*)d_in[18],  // conv
        (float*)d_out);
}

// round 4
// speedup vs baseline: 1.1892x; 1.1892x over previous
#include <cuda_runtime.h>
#include <math.h>

// ---------------------------------------------------------------------------
// Shapes
//   x0: [2, 256, 32^3]   -> 512 channel-slices of 32768 elems
//   x1: [2, 128, 64^3]   -> 256 channel-slices of 262144 elems
//   x2: [2,  64, 128^3]  -> 128 channel-slices of 2097152 elems
// Partial-sum layout (deterministic, no atomics):
//   x2: 32 partials/slice -> 4096 at g_part[0]
//   x1:  4 partials/slice -> 1024 at g_part[4096]
//   x0:  1 partial/slice  ->  512 at g_part[5120]
// ---------------------------------------------------------------------------

__device__ float g_part[5632];
__device__ float g_dummy[4];   // sink for L2-warm blocks (never read)

__global__ __launch_bounds__(256) void gap_reduce(
    const float* __restrict__ x0,
    const float* __restrict__ x1,
    const float* __restrict__ x2,
    const float* __restrict__ w_a,   // mlp_w1 (L2 warm, scheduled last)
    const float* __restrict__ w_b,   // mlp_w2
    const float* __restrict__ w_c)   // conv_w
{
    int bid = blockIdx.x;

    // --- L2 warm blocks (run last in wave order): pre-touch weights ---
    if (bid >= 5632) {
        const float* w = (bid == 5632) ? w_a : (bid == 5633) ? w_b : w_c;
        const float4* w4 = reinterpret_cast<const float4*>(w);
        float s = 0.f;
        for (int i = threadIdx.x; i < 7168; i += 256) {
            float4 a = w4[i];
            s += (a.x + a.y) + (a.z + a.w);
        }
        if (s == -1.0f && threadIdx.x == 0) g_dummy[bid - 5632] = s;
        return;
    }

    const float4* src;
    int nvec;
    if (bid < 4096) {                      // x2 chunks: 16384 float4
        src  = reinterpret_cast<const float4*>(x2) + (size_t)bid * 16384;
        nvec = 16384;
    } else if (bid < 5120) {               // x1 chunks: 16384 float4
        src  = reinterpret_cast<const float4*>(x1) + (size_t)(bid - 4096) * 16384;
        nvec = 16384;
    } else {                               // x0 chunks: 8192 float4
        src  = reinterpret_cast<const float4*>(x0) + (size_t)(bid - 5120) * 8192;
        nvec = 8192;
    }

    // Dual-accumulator streaming: 2 independent float4 loads per iteration.
    float s0 = 0.f, s1 = 0.f;
    #pragma unroll 4
    for (int i = threadIdx.x; i < nvec; i += 512) {
        float4 a = __ldcs(src + i);
        float4 b = __ldcs(src + i + 256);
        s0 += (a.x + a.y) + (a.z + a.w);
        s1 += (b.x + b.y) + (b.z + b.w);
    }
    float s = s0 + s1;

    __shared__ float sbuf[8];
    #pragma unroll
    for (int o = 16; o; o >>= 1) s += __shfl_down_sync(0xffffffffu, s, o);
    if ((threadIdx.x & 31) == 0) sbuf[threadIdx.x >> 5] = s;
    __syncthreads();
    if (threadIdx.x < 8) {
        s = sbuf[threadIdx.x];
        #pragma unroll
        for (int o = 4; o; o >>= 1) s += __shfl_down_sync(0x000000ffu, s, o);
        if (threadIdx.x == 0) g_part[bid] = s;
    }
}

// ---------------------------------------------------------------------------
// Epilogue: single block, 896 threads (warps 0-13 batch0, 14-27 batch1).
// All LN params/biases batch-loaded to smem up-front; weights L2-prefetched
// up-front so every later load is a hit.
// ---------------------------------------------------------------------------

__device__ __forceinline__ float gsum(float v, float* sbuf)
{
    #pragma unroll
    for (int o = 16; o; o >>= 1) v += __shfl_down_sync(0xffffffffu, v, o);
    int w = threadIdx.x >> 5;
    int lane = threadIdx.x & 31;
    if (lane == 0) sbuf[w] = v;
    __syncthreads();
    if (w == 0 || w == 14) {
        float x = (lane < 14) ? sbuf[w + lane] : 0.f;
        #pragma unroll
        for (int o = 16; o; o >>= 1) x += __shfl_down_sync(0xffffffffu, x, o);
        if (lane == 0) sbuf[w] = x;
    }
    __syncthreads();
    float r = sbuf[(threadIdx.x >= 448) ? 14 : 0];
    __syncthreads();
    return r;
}

__device__ __forceinline__ void ln_s(float* v, int n, int t,
                                     const float* w, const float* b,  // smem
                                     float* sbuf)
{
    float x   = (t < n) ? v[t] : 0.f;
    float mu  = gsum(x, sbuf) * (1.f / (float)n);
    float d   = (t < n) ? (x - mu) : 0.f;
    float var = gsum(d * d, sbuf) * (1.f / (float)n);
    float r   = rsqrtf(var + 1e-5f);
    if (t < n) v[t] = d * r * w[t] + b[t];
    __syncthreads();
}

__global__ __launch_bounds__(896) void epilogue(
    const float* __restrict__ ln1w, const float* __restrict__ ln1b,
    const float* __restrict__ ln2w, const float* __restrict__ ln2b,
    const float* __restrict__ ln3w, const float* __restrict__ ln3b,
    const float* __restrict__ ln4w, const float* __restrict__ ln4b,
    const float* __restrict__ ln5w, const float* __restrict__ ln5b,
    const float* __restrict__ mlp_w1, const float* __restrict__ mlp_b1,
    const float* __restrict__ mlp_w2, const float* __restrict__ mlp_b2,
    const float* __restrict__ conv_w, const float* __restrict__ conv_b,
    float* __restrict__ out)
{
    __shared__ float sv[2][448];
    __shared__ float h1s[2][64];
    __shared__ float red[2][448];
    __shared__ float sbuf[32];
    // LN params: w|b pairs, offsets: ln1@0(64), ln2@64(128), ln3@192(256),
    // ln4@448(384), ln5@832(448)  -> total 1280 each
    __shared__ float s_w[1280];
    __shared__ float s_b[1280];
    __shared__ float s_b1[64];
    __shared__ float s_b2[448];
    __shared__ float s_bc[64];

    int tid = threadIdx.x;

    // --- Fire-and-forget L2 prefetch of all weight matrices (2688 lines) ---
    {
        const char* w1 = (const char*)mlp_w1;
        const char* w2 = (const char*)mlp_w2;
        const char* wc = (const char*)conv_w;
        for (int p = tid; p < 896; p += 896) { } // (keep loop shape trivial)
        int p = tid;                 // 896 threads -> 1 line per matrix each
        asm volatile("prefetch.global.L2 [%0];" :: "l"(w1 + (size_t)p * 128));
        asm volatile("prefetch.global.L2 [%0];" :: "l"(w2 + (size_t)p * 128));
        asm volatile("prefetch.global.L2 [%0];" :: "l"(wc + (size_t)p * 128));
    }

    // --- Batch-load LN params + biases into smem (one parallel exposure) ---
    if (tid < 64)   { s_w[tid]       = ln1w[tid]; s_b[tid]       = ln1b[tid]; }
    if (tid < 128)  { s_w[64 + tid]  = ln2w[tid]; s_b[64 + tid]  = ln2b[tid]; }
    if (tid < 256)  { s_w[192 + tid] = ln3w[tid]; s_b[192 + tid] = ln3b[tid]; }
    if (tid < 384)  { s_w[448 + tid] = ln4w[tid]; s_b[448 + tid] = ln4b[tid]; }
    if (tid < 448)  { s_w[832 + tid] = ln5w[tid]; s_b[832 + tid] = ln5b[tid]; }
    if (tid < 64)   s_b1[tid] = mlp_b1[tid];
    if (tid < 448)  s_b2[tid] = mlp_b2[tid];
    if (tid >= 448 && tid < 512) s_bc[tid - 448] = conv_b[tid - 448];

    int b = tid / 448;
    int t = tid - b * 448;
    float* svb = sv[b];

    // --- Assemble raw GAP means (deterministic partial ordering) ---
    if (t < 64) {
        int base = (b * 64 + t) * 32;
        float s = 0.f;
        #pragma unroll
        for (int k = 0; k < 32; k++) s += g_part[base + k];
        svb[t] = s * (1.f / 2097152.f);
    }
    if (t < 128) {
        int base = 4096 + (b * 128 + t) * 4;
        float s = 0.f;
        #pragma unroll
        for (int k = 0; k < 4; k++) s += g_part[base + k];
        svb[64 + t] = s * (1.f / 262144.f);
    }
    if (t < 256) {
        svb[192 + t] = g_part[5120 + b * 256 + t] * (1.f / 32768.f);
    }
    __syncthreads();

    // --- LayerNorm chain (params from smem) ---
    ln_s(svb,        64, t, s_w,       s_b,       sbuf);
    ln_s(svb +  64, 128, t, s_w + 64,  s_b + 64,  sbuf);
    ln_s(svb + 192, 256, t, s_w + 192, s_b + 192, sbuf);
    ln_s(svb +  64, 384, t, s_w + 448, s_b + 448, sbuf);
    ln_s(svb,       448, t, s_w + 832, s_b + 832, sbuf);

    int c = t >> 6;                   // inner chunk 0..6
    int i = t & 63;                   // output index 0..63

    // --- h1 = relu(out7 @ W1^T + b1) ---
    {
        const float4* w4 = reinterpret_cast<const float4*>(mlp_w1 + i * 448 + c * 64);
        const float4* x4 = reinterpret_cast<const float4*>(svb + c * 64);
        float p = 0.f;
        #pragma unroll
        for (int k = 0; k < 16; k++) {
            float4 wv = w4[k], xv = x4[k];
            p = fmaf(wv.x, xv.x, p); p = fmaf(wv.y, xv.y, p);
            p = fmaf(wv.z, xv.z, p); p = fmaf(wv.w, xv.w, p);
        }
        red[b][c * 64 + i] = p;
    }
    __syncthreads();
    if (t < 64) {
        float acc = s_b1[t];
        #pragma unroll
        for (int cc = 0; cc < 7; cc++) acc += red[b][cc * 64 + t];
        h1s[b][t] = fmaxf(acc, 0.f);
    }
    __syncthreads();

    // --- h2 = relu(h1 @ W2^T + b2) ---
    {
        float acc = s_b2[t];
        const float4* w4 = reinterpret_cast<const float4*>(mlp_w2 + t * 64);
        const float4* h4 = reinterpret_cast<const float4*>(h1s[b]);
        #pragma unroll
        for (int k = 0; k < 16; k++) {
            float4 wv = w4[k], hv = h4[k];
            acc = fmaf(wv.x, hv.x, acc); acc = fmaf(wv.y, hv.y, acc);
            acc = fmaf(wv.z, hv.z, acc); acc = fmaf(wv.w, hv.w, acc);
        }
        acc = fmaxf(acc, 0.f);
        __syncthreads();
        svb[t] = acc;
        __syncthreads();
    }

    // --- o = sigmoid(h2 @ Wc^T + bc) ---
    {
        const float4* w4 = reinterpret_cast<const float4*>(conv_w + i * 448 + c * 64);
        const float4* x4 = reinterpret_cast<const float4*>(svb + c * 64);
        float p = 0.f;
        #pragma unroll
        for (int k = 0; k < 16; k++) {
            float4 wv = w4[k], xv = x4[k];
            p = fmaf(wv.x, xv.x, p); p = fmaf(wv.y, xv.y, p);
            p = fmaf(wv.z, xv.z, p); p = fmaf(wv.w, xv.w, p);
        }
        red[b][c * 64 + i] = p;
    }
    __syncthreads();
    if (t < 64) {
        float acc = s_bc[t];
        #pragma unroll
        for (int cc = 0; cc < 7; cc++) acc += red[b][cc * 64 + t];
        out[b * 64 + t] = 1.f / (1.f + expf(-acc));
    }
}

// ---------------------------------------------------------------------------

extern "C" void kernel_launch(void* const* d_in, const int* in_sizes, int n_in,
                              void* d_out, int out_size)
{
    const float* x0 = (const float*)d_in[0];
    const float* x1 = (const float*)d_in[1];
    const float* x2 = (const float*)d_in[2];

    gap_reduce<<<5635, 256>>>(x0, x1, x2,
                              (const float*)d_in[13],
                              (const float*)d_in[15],
                              (const float*)d_in[17]);

    epilogue<<<1, 896>>>(
        (const float*)d_in[3],  (const float*)d_in[4],
        (const float*)d_in[5],  (const float*)d_in[6],
        (const float*)d_in[7],  (const float*)d_in[8],
        (const float*)d_in[9],  (const float*)d_in[10],
        (const float*)d_in[11], (const float*)d_in[12],
        (const float*)d_in[13], (const float*)d_in[14],
        (const float*)d_in[15], (const float*)d_in[16],
        (const float*)d_in[17], (const float*)d_in[18],
        (float*)d_out);
}

// round 5
// speedup vs baseline: 1.2595x; 1.0592x over previous
#include <cuda_runtime.h>
#include <math.h>

// ---------------------------------------------------------------------------
// Shapes
//   x0: [2, 256, 32^3]   -> 512 channel-slices of 32768 elems
//   x1: [2, 128, 64^3]   -> 256 channel-slices of 262144 elems
//   x2: [2,  64, 128^3]  -> 128 channel-slices of 2097152 elems
// Partial-sum layout (deterministic, no atomics):
//   x2: 32 partials/slice -> 4096 at g_part[0]
//   x1:  4 partials/slice -> 1024 at g_part[4096]
//   x0:  1 partial/slice  ->  512 at g_part[5120]
// ---------------------------------------------------------------------------

__device__ float g_part[5632];
__device__ float g_dummy[4];   // sink for L2-warm blocks (never read)

__global__ __launch_bounds__(256) void gap_reduce(
    const float* __restrict__ x0,
    const float* __restrict__ x1,
    const float* __restrict__ x2,
    const float* __restrict__ w_a,   // mlp_w1 (L2 warm)
    const float* __restrict__ w_b,   // mlp_w2
    const float* __restrict__ w_c)   // conv_w
{
    int bid = blockIdx.x;

    // --- L2 warm blocks: pre-touch the weight matrices ---
    if (bid >= 5632) {
        const float* w = (bid == 5632) ? w_a : (bid == 5633) ? w_b : w_c;
        const float4* w4 = reinterpret_cast<const float4*>(w);
        float s = 0.f;
        for (int i = threadIdx.x; i < 7168; i += 256) {
            float4 a = w4[i];
            s += (a.x + a.y) + (a.z + a.w);
        }
        if (s == -1.0f && threadIdx.x == 0) g_dummy[bid - 5632] = s;
        return;
    }

    const float4* src;
    int nvec;
    if (bid < 4096) {                      // x2 chunks: 16384 float4
        src  = reinterpret_cast<const float4*>(x2) + (size_t)bid * 16384;
        nvec = 16384;
    } else if (bid < 5120) {               // x1 chunks: 16384 float4
        src  = reinterpret_cast<const float4*>(x1) + (size_t)(bid - 4096) * 16384;
        nvec = 16384;
    } else {                               // x0 chunks: 8192 float4
        src  = reinterpret_cast<const float4*>(x0) + (size_t)(bid - 5120) * 8192;
        nvec = 8192;
    }

    float s = 0.f;
    #pragma unroll 4
    for (int i = threadIdx.x; i < nvec; i += 256) {
        float4 a = __ldcs(src + i);        // streaming: evict-first in L2
        s += (a.x + a.y) + (a.z + a.w);
    }

    __shared__ float sbuf[8];
    #pragma unroll
    for (int o = 16; o; o >>= 1) s += __shfl_down_sync(0xffffffffu, s, o);
    if ((threadIdx.x & 31) == 0) sbuf[threadIdx.x >> 5] = s;
    __syncthreads();
    if (threadIdx.x < 8) {
        s = sbuf[threadIdx.x];
        #pragma unroll
        for (int o = 4; o; o >>= 1) s += __shfl_down_sync(0x000000ffu, s, o);
        if (threadIdx.x == 0) g_part[bid] = s;
    }
}

// ---------------------------------------------------------------------------
// Epilogue: single block, 896 threads = 28 warps.
// Warps 0-13 = batch 0, warps 14-27 = batch 1 for the LN chain.
// Matmuls use warp-per-output: lanes read consecutive float2s of one weight
// row (fully coalesced) and shuffle-reduce.
// ---------------------------------------------------------------------------

__device__ __forceinline__ float gsum(float v, float* sbuf)
{
    #pragma unroll
    for (int o = 16; o; o >>= 1) v += __shfl_down_sync(0xffffffffu, v, o);
    int w = threadIdx.x >> 5;
    int lane = threadIdx.x & 31;
    if (lane == 0) sbuf[w] = v;
    __syncthreads();
    if (w == 0 || w == 14) {
        float x = (lane < 14) ? sbuf[w + lane] : 0.f;
        #pragma unroll
        for (int o = 16; o; o >>= 1) x += __shfl_down_sync(0xffffffffu, x, o);
        if (lane == 0) sbuf[w] = x;
    }
    __syncthreads();
    float r = sbuf[(threadIdx.x >= 448) ? 14 : 0];
    __syncthreads();
    return r;
}

__device__ __forceinline__ void ln_s(float* v, int n, int t,
                                     const float* w, const float* b,  // smem
                                     float* sbuf)
{
    float x   = (t < n) ? v[t] : 0.f;
    float mu  = gsum(x, sbuf) * (1.f / (float)n);
    float d   = (t < n) ? (x - mu) : 0.f;
    float var = gsum(d * d, sbuf) * (1.f / (float)n);
    float r   = rsqrtf(var + 1e-5f);
    if (t < n) v[t] = d * r * w[t] + b[t];
    __syncthreads();
}

__device__ __forceinline__ float warp_red(float v)
{
    #pragma unroll
    for (int o = 16; o; o >>= 1) v += __shfl_down_sync(0xffffffffu, v, o);
    return v;
}

__global__ __launch_bounds__(896) void epilogue(
    const float* __restrict__ ln1w, const float* __restrict__ ln1b,
    const float* __restrict__ ln2w, const float* __restrict__ ln2b,
    const float* __restrict__ ln3w, const float* __restrict__ ln3b,
    const float* __restrict__ ln4w, const float* __restrict__ ln4b,
    const float* __restrict__ ln5w, const float* __restrict__ ln5b,
    const float* __restrict__ mlp_w1, const float* __restrict__ mlp_b1,
    const float* __restrict__ mlp_w2, const float* __restrict__ mlp_b2,
    const float* __restrict__ conv_w, const float* __restrict__ conv_b,
    float* __restrict__ out)
{
    __shared__ __align__(16) float sv[2][448];   // LN workspace / h2
    __shared__ __align__(16) float h1s[2][64];
    __shared__ float sbuf[32];
    // LN params packed: ln1@0(64) ln2@64(128) ln3@192(256) ln4@448(384) ln5@832(448)
    __shared__ float s_w[1280];
    __shared__ float s_b[1280];
    __shared__ float s_b1[64];
    __shared__ float s_b2[448];
    __shared__ float s_bc[64];

    int tid  = threadIdx.x;
    int wid  = tid >> 5;
    int lane = tid & 31;

    // --- Batch-load LN params + biases into smem (one parallel exposure) ---
    if (tid < 64)   { s_w[tid]       = ln1w[tid]; s_b[tid]       = ln1b[tid]; }
    if (tid < 128)  { s_w[64 + tid]  = ln2w[tid]; s_b[64 + tid]  = ln2b[tid]; }
    if (tid < 256)  { s_w[192 + tid] = ln3w[tid]; s_b[192 + tid] = ln3b[tid]; }
    if (tid < 384)  { s_w[448 + tid] = ln4w[tid]; s_b[448 + tid] = ln4b[tid]; }
    if (tid < 448)  { s_w[832 + tid] = ln5w[tid]; s_b[832 + tid] = ln5b[tid]; }
    if (tid < 64)   s_b1[tid] = mlp_b1[tid];
    if (tid < 448)  s_b2[tid] = mlp_b2[tid];
    if (tid >= 448 && tid < 512) s_bc[tid - 448] = conv_b[tid - 448];

    int b = tid / 448;
    int t = tid - b * 448;
    float* svb = sv[b];

    // --- Assemble raw GAP means (deterministic partial ordering) ---
    if (t < 64) {
        int base = (b * 64 + t) * 32;
        float s = 0.f;
        #pragma unroll
        for (int k = 0; k < 32; k++) s += g_part[base + k];
        svb[t] = s * (1.f / 2097152.f);
    }
    if (t < 128) {
        int base = 4096 + (b * 128 + t) * 4;
        float s = 0.f;
        #pragma unroll
        for (int k = 0; k < 4; k++) s += g_part[base + k];
        svb[64 + t] = s * (1.f / 262144.f);
    }
    if (t < 256) {
        svb[192 + t] = g_part[5120 + b * 256 + t] * (1.f / 32768.f);
    }
    __syncthreads();

    // --- LayerNorm chain (params from smem) ---
    ln_s(svb,        64, t, s_w,       s_b,       sbuf);
    ln_s(svb +  64, 128, t, s_w + 64,  s_b + 64,  sbuf);
    ln_s(svb + 192, 256, t, s_w + 192, s_b + 192, sbuf);
    ln_s(svb +  64, 384, t, s_w + 448, s_b + 448, sbuf);
    ln_s(svb,       448, t, s_w + 832, s_b + 832, sbuf);

    // =======================================================================
    // Stage 1: h1[b][o] = relu(b1[o] + w1[o,:] . sv[b])   (128 warp-tasks)
    // Lanes read consecutive float2s of row o -> coalesced 256B wavefronts.
    // =======================================================================
    #pragma unroll
    for (int j = 0; j < 5; j++) {
        int tau = j * 28 + wid;
        if (tau < 128) {
            int bb = tau >> 6;
            int o  = tau & 63;
            const float2* wr = reinterpret_cast<const float2*>(mlp_w1 + o * 448);
            const float2* xr = reinterpret_cast<const float2*>(sv[bb]);
            float p = 0.f;
            #pragma unroll
            for (int m = 0; m < 7; m++) {
                float2 wv = wr[m * 32 + lane];
                float2 xv = xr[m * 32 + lane];
                p = fmaf(wv.x, xv.x, p);
                p = fmaf(wv.y, xv.y, p);
            }
            p = warp_red(p);
            if (lane == 0) h1s[bb][o] = fmaxf(s_b1[o] + p, 0.f);
        }
    }
    __syncthreads();

    // =======================================================================
    // Stage 2: h2[b][j] = relu(b2[j] + w2[j,:] . h1[b])   (896 warp-tasks)
    // One row (64 floats) per task; lane reads one float2 -> coalesced 256B.
    // Results overwrite sv (LN output fully consumed by stage 1).
    // =======================================================================
    {
        int base = wid * 32;
        #pragma unroll
        for (int i = 0; i < 32; i++) {
            int tau = base + i;
            int bb  = tau >= 448;
            int jj  = tau - bb * 448;
            const float2* wr = reinterpret_cast<const float2*>(mlp_w2 + jj * 64);
            const float2* hr = reinterpret_cast<const float2*>(h1s[bb]);
            float2 wv = wr[lane];
            float2 hv = hr[lane];
            float p = warp_red(fmaf(wv.x, hv.x, wv.y * hv.y));
            if (lane == 0) sv[bb][jj] = fmaxf(s_b2[jj] + p, 0.f);
        }
    }
    __syncthreads();

    // =======================================================================
    // Stage 3: o[b][o] = sigmoid(bc[o] + wc[o,:] . h2[b])  (128 warp-tasks)
    // =======================================================================
    #pragma unroll
    for (int j = 0; j < 5; j++) {
        int tau = j * 28 + wid;
        if (tau < 128) {
            int bb = tau >> 6;
            int o  = tau & 63;
            const float2* wr = reinterpret_cast<const float2*>(conv_w + o * 448);
            const float2* xr = reinterpret_cast<const float2*>(sv[bb]);
            float p = 0.f;
            #pragma unroll
            for (int m = 0; m < 7; m++) {
                float2 wv = wr[m * 32 + lane];
                float2 xv = xr[m * 32 + lane];
                p = fmaf(wv.x, xv.x, p);
                p = fmaf(wv.y, xv.y, p);
            }
            p = warp_red(p);
            if (lane == 0) {
                float acc = s_bc[o] + p;
                out[bb * 64 + o] = 1.f / (1.f + expf(-acc));
            }
        }
    }
}

// ---------------------------------------------------------------------------

extern "C" void kernel_launch(void* const* d_in, const int* in_sizes, int n_in,
                              void* d_out, int out_size)
{
    const float* x0 = (const float*)d_in[0];
    const float* x1 = (const float*)d_in[1];
    const float* x2 = (const float*)d_in[2];

    gap_reduce<<<5635, 256>>>(x0, x1, x2,
                              (const float*)d_in[13],
                              (const float*)d_in[15],
                              (const float*)d_in[17]);

    epilogue<<<1, 896>>>(
        (const float*)d_in[3],  (const float*)d_in[4],
        (const float*)d_in[5],  (const float*)d_in[6],
        (const float*)d_in[7],  (const float*)d_in[8],
        (const float*)d_in[9],  (const float*)d_in[10],
        (const float*)d_in[11], (const float*)d_in[12],
        (const float*)d_in[13], (const float*)d_in[14],
        (const float*)d_in[15], (const float*)d_in[16],
        (const float*)d_in[17], (const float*)d_in[18],
        (float*)d_out);
}